// round 13
// baseline (speedup 1.0000x reference)
#include <cuda_runtime.h>
#include <math.h>

#define N_PIX_MAX 4194304
#define N_BINS    350000
#define TAPS      901
#define HALF      450
#define CHALF     900                       // composite kernel half-width
#define COMP_N    2112                      // composite kernel storage (>=1801)
#define CONV_THREADS 256
#define RPT       8                         // float2 output-pairs per thread
#define RING      8                         // u64 ring slots (elements mod 8)
#define HTILE     (CONV_THREADS * RPT)      // 2048 (per half)
#define TILE_OUT  (2 * HTILE)               // 4096 outputs per block
#define RAW2      (HTILE + 2*CHALF + 16)    // 3864 float2 window (+refill slack)
#define PAD2      (RAW2 + (RAW2 >> 3))      // bank-conflict padding (1 per 8)
#define WSH2_N    512                       // composite support slots (<=504 taps)
#define P2(i)     ((i) + ((i) >> 3))
#define EW        456                       // edge-exact region per side
#define ESLICES   8                         // blocks per side for edge kernel
#define EOUT      (EW / ESLICES)            // 57 outputs per edge block
#define SMID_B    320                       // per-block mid slots (needs ~161)
#define SF_B      512                       // per-block f slots (needs ~294)

typedef unsigned long long u64;

// ---------------- device scratch (no allocations allowed) ----------------
__device__ float g_rot[TAPS];
__device__ float g_gauss[TAPS];
__device__ float g_comp[COMP_N];            // composite kernel K = k1 (*) k2
__device__ int   g_lo8;                     // composite support lo, 8-aligned
__device__ int   g_nblk;                    // # of 8-tap blocks
__device__ int   g_b[4];                    // lo0, hi0, lo1, hi1 (exact bounds)
__device__ __align__(16) float g_conv[N_PIX_MAX];   // conv result
__device__ float g_sums[N_BINS];
__device__ float g_cnts[N_BINS];

// ---------------- zero the bin accumulators (graph replays!) -------------
__global__ void zero_kernel() {
    int i = blockIdx.x * blockDim.x + threadIdx.x;
    int stride = gridDim.x * blockDim.x;
    for (int j = i; j < N_BINS; j += stride) {
        g_sums[j] = 0.0f;
        g_cnts[j] = 0.0f;
    }
}

// ------- build k1, k2, composite K = k1*k2, and support bounds -----------
__global__ void setup_kernel(const float* __restrict__ ln_sigma,
                             const float* __restrict__ ln_vsini) {
    __shared__ float red[1024];
    __shared__ float sk1[904], sk2[904];
    __shared__ int s_lo0, s_hi0, s_lo1, s_hi1;
    int tid = threadIdx.x;
    if (tid == 0) { s_lo0 = TAPS; s_hi0 = -1; s_lo1 = TAPS; s_hi1 = -1; }
    __syncthreads();

    float vsini = 0.9f + expf(ln_vsini[0]);
    float sigma = 0.01f + expf(ln_sigma[0]);

    float w  = 0.0f;   // rotational tap (pre-normalization)
    float gw = 0.0f;   // gaussian tap
    if (tid < TAPS) {
        float g = -4.5f + 0.01f * (float)tid;   // linspace(-4.5,4.5,901)
        float x  = (299792.458f * g / 10500.0f) / vsini;
        float x2 = fminf(x * x, 1.0f);
        if (x2 < 0.99999999f) {
            w = 2.0f * sqrtf(1.0f - x2);
            atomicMin(&s_lo0, tid);
            atomicMax(&s_hi0, tid);
        }
        float e = expf(-0.5f * g * g / (sigma * sigma));
        // ~4.5-sigma cutoff: truncated tail mass ~3.4e-6 relative (<< 1e-3 tol)
        if (e >= 4e-5f) {
            atomicMin(&s_lo1, tid);
            atomicMax(&s_hi1, tid);
        }
        gw = (0.01f / (sigma * sqrtf(2.0f * 3.1415926654f))) * e;
    }

    // block sum of rotational kernel for normalization
    red[tid] = w;
    __syncthreads();
    for (int s = 512; s > 0; s >>= 1) {
        if (tid < s) red[tid] += red[tid + s];
        __syncthreads();
    }
    float total = red[0];

    if (tid < TAPS) {
        float k1 = w / total;
        sk1[tid] = k1;  g_rot[tid]   = k1;
        sk2[tid] = gw;  g_gauss[tid] = gw;
    } else if (tid < 904) {
        sk1[tid] = 0.0f;
        sk2[tid] = 0.0f;
    }
    __syncthreads();

    // composite K[c] = sum_a k1[a] * k2[c-a]; support [lo0+lo1, hi0+hi1]
    int lo0 = s_lo0, hi0 = s_hi0, lo1 = s_lo1, hi1 = s_hi1;
    for (int c = tid; c < COMP_N; c += 1024) {
        float s = 0.0f;
        int a0 = max(lo0, c - hi1);
        int a1 = min(hi0, c - lo1);
        for (int a = a0; a <= a1; ++a)
            s += sk1[a] * sk2[c - a];
        g_comp[c] = s;
    }
    if (tid == 0) {
        int lo = lo0 + lo1;
        int hi = hi0 + hi1;
        int lo8 = lo & ~7;
        int nblk = ((hi - lo8 + 1) + 7) >> 3;
        if (nblk > (WSH2_N - 8) / 8) nblk = (WSH2_N - 8) / 8;  // safety clamp
        g_lo8  = lo8;
        g_nblk = nblk;
        g_b[0] = lo0; g_b[1] = hi0; g_b[2] = lo1; g_b[3] = hi1;
    }
}

// -------- fused tiled conv (composite kernel), f32x2 sliding ring --------
// Single pass: out[i] = sum_c K[c] * f[i + c - 900].  Incremental swizzled
// indexing, packed {w,w} weights, 1-tap weight prefetch.
__global__ void __launch_bounds__(CONV_THREADS, 5)
conv_kernel(const float* __restrict__ in, int n) {
    __shared__ float2 sh2[PAD2];
    __shared__ float2 wsh2[WSH2_N];

    const int lo8  = g_lo8;            // multiple of 8
    const int nblk = g_nblk;           // number of 8-tap blocks

    const int tile0 = blockIdx.x * TILE_OUT;
    const int tid   = threadIdx.x;

    for (int j = tid; j < WSH2_N; j += CONV_THREADS) {
        int c = lo8 + j;
        float wv = (c < COMP_N) ? g_comp[c] : 0.0f;
        wsh2[j] = make_float2(wv, wv);
    }
    for (int j = tid; j < RAW2; j += CONV_THREADS) {
        int g1 = tile0 - CHALF + j;
        int g2 = g1 + HTILE;
        float a = (g1 >= 0 && g1 < n) ? in[g1] : 0.0f;
        float b = (g2 >= 0 && g2 < n) ? in[g2] : 0.0f;
        sh2[P2(j)] = make_float2(a, b);
    }
    __syncthreads();

    const int base = tid * RPT;        // float2-index of first output pair
    u64 x[RING], acc[RPT];
    int roff = P2(base + lo8);         // padded index of ring start
#pragma unroll
    for (int s = 0; s < RING; ++s) {
        x[s]   = *(const u64*)&sh2[roff + s];     // P2(k0+s)=P2(k0)+s, s<8
        acc[s] = 0ull;                 // (0.0f, 0.0f)
    }
    roff += 9;                         // refill base: P2(k0+8) = P2(k0)+9

    int woff = 0;                      // weight index within wsh2
    u64 wp_cur = *(const u64*)&wsh2[0];          // prefetched packed weight
    for (int b = 0; b < nblk; ++b) {
#pragma unroll
        for (int u = 0; u < 8; ++u) {  // tap c = lo8 + 8*b + u
            u64 wp_nxt = *(const u64*)&wsh2[woff + u + 1];  // prefetch next tap
            // r=0 is the last consumer of slot u -> FMA first, then refill
            asm("fma.rn.f32x2 %0, %1, %2, %0;"
                : "+l"(acc[0]) : "l"(x[u]), "l"(wp_cur));
            u64 xfill = *(const u64*)&sh2[roff + u];        // element tap+8
#pragma unroll
            for (int r = 1; r < RPT; ++r) {
                asm("fma.rn.f32x2 %0, %1, %2, %0;"
                    : "+l"(acc[r]) : "l"(x[(u + r) & 7]), "l"(wp_cur));
            }
            x[u] = xfill;
            wp_cur = wp_nxt;
        }
        roff += 9;                     // next block's refill base
        woff += 8;
    }

    // unpack: low 32 bits = first-half output, high = second-half
    float lo_v[RPT], hi_v[RPT];
#pragma unroll
    for (int r = 0; r < RPT; ++r) {
        lo_v[r] = __int_as_float((int)(acc[r] & 0xFFFFFFFFull));
        hi_v[r] = __int_as_float((int)(acc[r] >> 32));
    }

    int o1 = tile0 + base;
    int o2 = o1 + HTILE;
    if (o1 + RPT <= n) {
        *(float4*)(g_conv + o1)     = make_float4(lo_v[0], lo_v[1], lo_v[2], lo_v[3]);
        *(float4*)(g_conv + o1 + 4) = make_float4(lo_v[4], lo_v[5], lo_v[6], lo_v[7]);
    } else {
#pragma unroll
        for (int r = 0; r < RPT; ++r)
            if (o1 + r < n) g_conv[o1 + r] = lo_v[r];
    }
    if (o2 + RPT <= n) {
        *(float4*)(g_conv + o2)     = make_float4(hi_v[0], hi_v[1], hi_v[2], hi_v[3]);
        *(float4*)(g_conv + o2 + 4) = make_float4(hi_v[4], hi_v[5], hi_v[6], hi_v[7]);
    } else {
#pragma unroll
        for (int r = 0; r < RPT; ++r)
            if (o2 + r < n) g_conv[o2 + r] = hi_v[r];
    }
}

// ------- exact two-stage recompute of the first/last EW outputs ----------
// 16 blocks (8 slices per side), warp-per-element with lane-split taps and
// shuffle reduction. Each block stages only its needed f window (<=~294
// floats) and both kernels in smem.
__global__ void __launch_bounds__(256)
edge_kernel(const float* __restrict__ f, int n) {
    __shared__ float sk1[904], sk2[904];
    __shared__ float smid[SMID_B];
    __shared__ float sf[SF_B];

    const int tid  = threadIdx.x;
    const int wid  = tid >> 5;
    const int lane = tid & 31;
    const int side = blockIdx.x >> 3;          // 0 = low edge, 1 = high edge
    const int sl   = blockIdx.x & 7;           // slice within side

    for (int j = tid; j < 904; j += 256) {
        sk1[j] = (j < TAPS) ? g_rot[j]   : 0.0f;
        sk2[j] = (j < TAPS) ? g_gauss[j] : 0.0f;
    }

    const int lo0 = g_b[0], hi0 = g_b[1], lo1 = g_b[2], hi1 = g_b[3];

    // this block's outputs: [obase, obase+EOUT)
    const int obase = side ? (n - EW + sl * EOUT) : (sl * EOUT);

    // mids needed: j in [obase+lo1-450, obase+EOUT-1+hi1-450] ∩ [0,n)
    int jlo = obase + lo1 - HALF;            if (jlo < 0) jlo = 0;
    int jhi = obase + EOUT - 1 + hi1 - HALF; if (jhi > n - 1) jhi = n - 1;
    int nm  = jhi - jlo + 1;                 if (nm > SMID_B) nm = SMID_B;

    // f needed for those mids: fi in [jlo+lo0-450, jhi+hi0-450] ∩ [0,n)
    int flo = jlo + lo0 - HALF;              if (flo < 0) flo = 0;
    int fhi = jhi + hi0 - HALF;              if (fhi > n - 1) fhi = n - 1;
    int nf  = fhi - flo + 1;                 if (nf > SF_B) nf = SF_B;

    for (int j = tid; j < nf; j += 256)
        sf[j] = f[flo + j];
    __syncthreads();

    // stage 1: warp-per-mid, lanes stride taps, shuffle reduce
    for (int mm = wid; mm < nm; mm += 8) {
        int j = jlo + mm;
        float p = 0.0f;
        for (int a = lo0 + lane; a <= hi0; a += 32) {
            int fi = j + a - HALF;
            if (fi >= 0 && fi < n)
                p += sk1[a] * sf[fi - flo];
        }
#pragma unroll
        for (int o = 16; o > 0; o >>= 1)
            p += __shfl_xor_sync(0xFFFFFFFFu, p, o);
        if (lane == 0) smid[mm] = p;
    }
    __syncthreads();

    // stage 2: warp-per-output, lanes stride taps, shuffle reduce
    for (int il = wid; il < EOUT; il += 8) {
        int i = obase + il;
        if (i < 0 || i >= n) continue;
        float p = 0.0f;
        for (int b = lo1 + lane; b <= hi1; b += 32) {
            int j = i + b - HALF;
            if (j >= 0 && j < n) {
                int mm = j - jlo;
                if (mm >= 0 && mm < nm)       // structurally always true
                    p += sk2[b] * smid[mm];
            }
        }
#pragma unroll
        for (int o = 16; o > 0; o >>= 1)
            p += __shfl_xor_sync(0xFFFFFFFFu, p, o);
        if (lane == 0) g_conv[i] = p;
    }
}

// ---------------- sorted segment sum/count (run-length + atomics) --------
__global__ void seg_kernel(const int* __restrict__ ids, int n) {
    long long tidg = (long long)(blockIdx.x * blockDim.x + threadIdx.x);
    int base = (int)(tidg * 8);
    if (base >= n) return;
    int end = base + 8;
    if (end > n) end = n;

    int   cur = ids[base];
    float s = 0.0f, c = 0.0f;
    for (int k = base; k < end; ++k) {
        int id = ids[k];
        if (id != cur) {
            atomicAdd(&g_sums[cur], s);
            atomicAdd(&g_cnts[cur], c);
            cur = id; s = 0.0f; c = 0.0f;
        }
        s += g_conv[k];
        c += 1.0f;
    }
    atomicAdd(&g_sums[cur], s);
    atomicAdd(&g_cnts[cur], c);
}

// ---------------- means, clip, drop first/last bin -----------------------
__global__ void final_kernel(float* __restrict__ out, int n_out) {
    int i = blockIdx.x * blockDim.x + threadIdx.x;
    if (i < n_out) {
        int id = i + 1;
        float c = g_cnts[id];
        float m = g_sums[id] / fmaxf(c, 1.0f);
        out[i] = fminf(fmaxf(m, 0.0f), 1.0f);
    }
}

extern "C" void kernel_launch(void* const* d_in, const int* in_sizes, int n_in,
                              void* d_out, int out_size) {
    const float* flux     = (const float*)d_in[0];
    const float* ln_sigma = (const float*)d_in[1];
    const float* ln_vsini = (const float*)d_in[2];
    const int*   ids      = (const int*)d_in[3];
    int n = in_sizes[0];

    zero_kernel<<<684, 512>>>();
    setup_kernel<<<1, 1024>>>(ln_sigma, ln_vsini);

    int conv_blocks = (n + TILE_OUT - 1) / TILE_OUT;
    conv_kernel<<<conv_blocks, CONV_THREADS>>>(flux, n);
    edge_kernel<<<2 * ESLICES, 256>>>(flux, n);

    int seg_threads = (n + 7) / 8;
    seg_kernel<<<(seg_threads + 255) / 256, 256>>>(ids, n);

    final_kernel<<<(out_size + 255) / 256, 256>>>((float*)d_out, out_size);
}

// round 14
// speedup vs baseline: 1.1800x; 1.1800x over previous
#include <cuda_runtime.h>
#include <math.h>

#define N_PIX_MAX 4194304
#define N_BINS    350000
#define TAPS      901
#define HALF      450
#define CHALF     900                       // composite kernel half-width
#define COMP_N    2112                      // composite kernel storage (>=1801)
#define CONV_THREADS 256
#define RPT       8                         // float2 output-pairs per thread
#define RING      8                         // u64 ring slots (elements mod 8)
#define HTILE     (CONV_THREADS * RPT)      // 2048 (per half)
#define TILE_OUT  (2 * HTILE)               // 4096 outputs per block
#define RAW2      (HTILE + 2*CHALF + 16)    // 3864 float2 window (+refill slack)
#define PAD2      (RAW2 + (RAW2 >> 3))      // bank-conflict padding (1 per 8)
#define WSH2_N    512                       // composite support slots (<=504 taps)
#define P2(i)     ((i) + ((i) >> 3))
#define JMAX      80                        // max one-sided mid-overhang (~66)
#define NC        64                        // corrected outputs per side

typedef unsigned long long u64;

// ---------------- device scratch (no allocations allowed) ----------------
__device__ float g_rot[TAPS];
__device__ float g_gauss[TAPS];
__device__ float g_comp[COMP_N];            // composite kernel K = k1 (*) k2
__device__ int   g_lo8;                     // composite support lo, 8-aligned
__device__ int   g_nblk;                    // # of 8-tap blocks
__device__ float g_corr_lo[NC];             // boundary corrections, low side
__device__ float g_corr_hi[NC];             // boundary corrections, high side
__device__ __align__(16) float g_conv[N_PIX_MAX];   // conv result
__device__ float g_sums[N_BINS];
__device__ float g_cnts[N_BINS];

// ---------------- zero the bin accumulators (graph replays!) -------------
__global__ void zero_kernel() {
    int i = blockIdx.x * blockDim.x + threadIdx.x;
    int stride = gridDim.x * blockDim.x;
    for (int j = i; j < N_BINS; j += stride) {
        g_sums[j] = 0.0f;
        g_cnts[j] = 0.0f;
    }
}

// ------- build k1, k2, composite K = k1*k2, and boundary corrections -----
// Composite conv with zero-padded f differs from the reference two-pass
// only via the clipping of the intermediate 'mid' to [0,n):
//   out2[i] = outc[i] - sum_{j<0 or j>=n} k2[j-i+450] * mid[j]
// mid[j] is nonzero outside [0,n) only within ~(hi0-450) of each boundary,
// so the correction touches only the first/last ~52 outputs. Compute it
// here (k1,k2 already in smem; needs only f[0..JL) and f[n-JH..n)).
__global__ void setup_kernel(const float* __restrict__ ln_sigma,
                             const float* __restrict__ ln_vsini,
                             const float* __restrict__ f, int n) {
    __shared__ float red[1024];
    __shared__ float sk1[904], sk2[904];
    __shared__ float sfl[JMAX], sfh[JMAX];      // f near low/high boundary
    __shared__ float smidl[JMAX], smidh[JMAX];  // mid[-1-t], mid[n+t]
    __shared__ int s_lo0, s_hi0, s_lo1, s_hi1;
    int tid = threadIdx.x;
    if (tid == 0) { s_lo0 = TAPS; s_hi0 = -1; s_lo1 = TAPS; s_hi1 = -1; }
    __syncthreads();

    float vsini = 0.9f + expf(ln_vsini[0]);
    float sigma = 0.01f + expf(ln_sigma[0]);

    float w  = 0.0f;   // rotational tap (pre-normalization)
    float gw = 0.0f;   // gaussian tap
    if (tid < TAPS) {
        float g = -4.5f + 0.01f * (float)tid;   // linspace(-4.5,4.5,901)
        float x  = (299792.458f * g / 10500.0f) / vsini;
        float x2 = fminf(x * x, 1.0f);
        if (x2 < 0.99999999f) {
            w = 2.0f * sqrtf(1.0f - x2);
            atomicMin(&s_lo0, tid);
            atomicMax(&s_hi0, tid);
        }
        float e = expf(-0.5f * g * g / (sigma * sigma));
        // ~4.5-sigma cutoff: truncated tail mass ~3.4e-6 relative (<< 1e-3 tol)
        if (e >= 4e-5f) {
            atomicMin(&s_lo1, tid);
            atomicMax(&s_hi1, tid);
        }
        gw = (0.01f / (sigma * sqrtf(2.0f * 3.1415926654f))) * e;
    }

    // block sum of rotational kernel for normalization
    red[tid] = w;
    __syncthreads();
    for (int s = 512; s > 0; s >>= 1) {
        if (tid < s) red[tid] += red[tid + s];
        __syncthreads();
    }
    float total = red[0];

    if (tid < TAPS) {
        float k1 = w / total;
        sk1[tid] = k1;  g_rot[tid]   = k1;
        sk2[tid] = gw;  g_gauss[tid] = gw;
    } else if (tid < 904) {
        sk1[tid] = 0.0f;
        sk2[tid] = 0.0f;
    }
    __syncthreads();

    // composite K[c] = sum_a k1[a] * k2[c-a]; support [lo0+lo1, hi0+hi1]
    int lo0 = s_lo0, hi0 = s_hi0, lo1 = s_lo1, hi1 = s_hi1;
    for (int c = tid; c < COMP_N; c += 1024) {
        float s = 0.0f;
        int a0 = max(lo0, c - hi1);
        int a1 = min(hi0, c - lo1);
        for (int a = a0; a <= a1; ++a)
            s += sk1[a] * sk2[c - a];
        g_comp[c] = s;
    }
    if (tid == 0) {
        int lo = lo0 + lo1;
        int hi = hi0 + hi1;
        int lo8 = lo & ~7;
        int nblk = ((hi - lo8 + 1) + 7) >> 3;
        if (nblk > (WSH2_N - 8) / 8) nblk = (WSH2_N - 8) / 8;  // safety clamp
        g_lo8  = lo8;
        g_nblk = nblk;
    }

    // ---- boundary corrections ----
    int JL = hi0 - HALF;  if (JL < 0) JL = 0;  if (JL > JMAX) JL = JMAX;
    int JH = HALF - lo0;  if (JH < 0) JH = 0;  if (JH > JMAX) JH = JMAX;

    for (int j = tid; j < JL; j += 1024) sfl[j] = f[j];
    for (int j = tid; j < JH; j += 1024) sfh[j] = f[n - 1 - j];  // sfh[m]=f[n-1-m]
    __syncthreads();

    // mid values outside [0,n):
    // smidl[jn-1] = mid[-jn] = sum_m k1[m+450+jn] * f[m],       m in [0, hi0-450-jn]
    // smidh[jn-1] = mid[n-1+jn] = sum_m k1[450-jn-m] * f[n-1-m], m in [0, 450-jn-lo0]
    if (tid < JL) {
        int jn = tid + 1;
        float s = 0.0f;
        int mmax = hi0 - HALF - jn;
        for (int m = 0; m <= mmax; ++m)
            s += sk1[m + HALF + jn] * sfl[m];
        smidl[tid] = s;
    } else if (tid >= 128 && tid - 128 < JH) {
        int jn = tid - 127;
        float s = 0.0f;
        int mmax = HALF - jn - lo0;
        for (int m = 0; m <= mmax; ++m)
            s += sk1[HALF - jn - m] * sfh[m];
        smidh[jn - 1] = s;
    }
    __syncthreads();

    // corrections:
    // corr_lo[i]  = sum_jn k2[450-i-jn]  * smidl[jn-1],  i in [0,NC)
    // corr_hi[ii] = sum_jn k2[513+jn-ii] * smidh[jn-1],  output i = n-NC+ii
    if (tid >= 256 && tid < 256 + NC) {
        int i = tid - 256;
        float s = 0.0f;
        for (int jn = 1; jn <= JL; ++jn) {
            int idx = HALF - i - jn;
            if (idx >= 0) s += sk2[idx] * smidl[jn - 1];
        }
        g_corr_lo[i] = s;
    } else if (tid >= 384 && tid < 384 + NC) {
        int ii = tid - 384;                    // output i = n - NC + ii
        float s = 0.0f;
        for (int jn = 1; jn <= JH; ++jn) {
            int idx = (NC - 1 - ii) + HALF + jn;   // = jn - ii + 513 for NC=64
            if (idx <= 900) s += sk2[idx] * smidh[jn - 1];
        }
        g_corr_hi[ii] = s;
    }
}

// -------- fused tiled conv (composite kernel), f32x2 sliding ring --------
// Single pass: out[i] = sum_c K[c] * f[i + c - 900].  Incremental swizzled
// indexing, packed {w,w} weights, 1-tap weight prefetch. Block 0 and the
// last block subtract the precomputed boundary corrections during the store.
__global__ void __launch_bounds__(CONV_THREADS, 5)
conv_kernel(const float* __restrict__ in, int n) {
    __shared__ float2 sh2[PAD2];
    __shared__ float2 wsh2[WSH2_N];

    const int lo8  = g_lo8;            // multiple of 8
    const int nblk = g_nblk;           // number of 8-tap blocks

    const int tile0 = blockIdx.x * TILE_OUT;
    const int tid   = threadIdx.x;

    for (int j = tid; j < WSH2_N; j += CONV_THREADS) {
        int c = lo8 + j;
        float wv = (c < COMP_N) ? g_comp[c] : 0.0f;
        wsh2[j] = make_float2(wv, wv);
    }
    for (int j = tid; j < RAW2; j += CONV_THREADS) {
        int g1 = tile0 - CHALF + j;
        int g2 = g1 + HTILE;
        float a = (g1 >= 0 && g1 < n) ? in[g1] : 0.0f;
        float b = (g2 >= 0 && g2 < n) ? in[g2] : 0.0f;
        sh2[P2(j)] = make_float2(a, b);
    }
    __syncthreads();

    const int base = tid * RPT;        // float2-index of first output pair
    u64 x[RING], acc[RPT];
    int roff = P2(base + lo8);         // padded index of ring start
#pragma unroll
    for (int s = 0; s < RING; ++s) {
        x[s]   = *(const u64*)&sh2[roff + s];     // P2(k0+s)=P2(k0)+s, s<8
        acc[s] = 0ull;                 // (0.0f, 0.0f)
    }
    roff += 9;                         // refill base: P2(k0+8) = P2(k0)+9

    int woff = 0;                      // weight index within wsh2
    u64 wp_cur = *(const u64*)&wsh2[0];          // prefetched packed weight
    for (int b = 0; b < nblk; ++b) {
#pragma unroll
        for (int u = 0; u < 8; ++u) {  // tap c = lo8 + 8*b + u
            u64 wp_nxt = *(const u64*)&wsh2[woff + u + 1];  // prefetch next tap
            // r=0 is the last consumer of slot u -> FMA first, then refill
            asm("fma.rn.f32x2 %0, %1, %2, %0;"
                : "+l"(acc[0]) : "l"(x[u]), "l"(wp_cur));
            u64 xfill = *(const u64*)&sh2[roff + u];        // element tap+8
#pragma unroll
            for (int r = 1; r < RPT; ++r) {
                asm("fma.rn.f32x2 %0, %1, %2, %0;"
                    : "+l"(acc[r]) : "l"(x[(u + r) & 7]), "l"(wp_cur));
            }
            x[u] = xfill;
            wp_cur = wp_nxt;
        }
        roff += 9;                     // next block's refill base
        woff += 8;
    }

    // unpack: low 32 bits = first-half output, high = second-half
    float lo_v[RPT], hi_v[RPT];
#pragma unroll
    for (int r = 0; r < RPT; ++r) {
        lo_v[r] = __int_as_float((int)(acc[r] & 0xFFFFFFFFull));
        hi_v[r] = __int_as_float((int)(acc[r] >> 32));
    }

    int o1 = tile0 + base;
    int o2 = o1 + HTILE;

    // boundary corrections (only 16 threads chip-wide take these)
    if (blockIdx.x == 0 && tid < (NC / RPT)) {
#pragma unroll
        for (int r = 0; r < RPT; ++r)
            lo_v[r] -= g_corr_lo[base + r];          // outputs 0..NC-1
    }
    if (blockIdx.x == gridDim.x - 1) {
#pragma unroll
        for (int r = 0; r < RPT; ++r) {
            int idx = o2 + r - (n - NC);
            if (idx >= 0 && idx < NC) hi_v[r] -= g_corr_hi[idx];
        }
    }

    if (o1 + RPT <= n) {
        *(float4*)(g_conv + o1)     = make_float4(lo_v[0], lo_v[1], lo_v[2], lo_v[3]);
        *(float4*)(g_conv + o1 + 4) = make_float4(lo_v[4], lo_v[5], lo_v[6], lo_v[7]);
    } else {
#pragma unroll
        for (int r = 0; r < RPT; ++r)
            if (o1 + r < n) g_conv[o1 + r] = lo_v[r];
    }
    if (o2 + RPT <= n) {
        *(float4*)(g_conv + o2)     = make_float4(hi_v[0], hi_v[1], hi_v[2], hi_v[3]);
        *(float4*)(g_conv + o2 + 4) = make_float4(hi_v[4], hi_v[5], hi_v[6], hi_v[7]);
    } else {
#pragma unroll
        for (int r = 0; r < RPT; ++r)
            if (o2 + r < n) g_conv[o2 + r] = hi_v[r];
    }
}

// ---------------- sorted segment sum/count (run-length + atomics) --------
__global__ void seg_kernel(const int* __restrict__ ids, int n) {
    long long tidg = (long long)(blockIdx.x * blockDim.x + threadIdx.x);
    int base = (int)(tidg * 8);
    if (base >= n) return;
    int end = base + 8;
    if (end > n) end = n;

    int   cur = ids[base];
    float s = 0.0f, c = 0.0f;
    for (int k = base; k < end; ++k) {
        int id = ids[k];
        if (id != cur) {
            atomicAdd(&g_sums[cur], s);
            atomicAdd(&g_cnts[cur], c);
            cur = id; s = 0.0f; c = 0.0f;
        }
        s += g_conv[k];
        c += 1.0f;
    }
    atomicAdd(&g_sums[cur], s);
    atomicAdd(&g_cnts[cur], c);
}

// ---------------- means, clip, drop first/last bin -----------------------
__global__ void final_kernel(float* __restrict__ out, int n_out) {
    int i = blockIdx.x * blockDim.x + threadIdx.x;
    if (i < n_out) {
        int id = i + 1;
        float c = g_cnts[id];
        float m = g_sums[id] / fmaxf(c, 1.0f);
        out[i] = fminf(fmaxf(m, 0.0f), 1.0f);
    }
}

extern "C" void kernel_launch(void* const* d_in, const int* in_sizes, int n_in,
                              void* d_out, int out_size) {
    const float* flux     = (const float*)d_in[0];
    const float* ln_sigma = (const float*)d_in[1];
    const float* ln_vsini = (const float*)d_in[2];
    const int*   ids      = (const int*)d_in[3];
    int n = in_sizes[0];

    zero_kernel<<<684, 512>>>();
    setup_kernel<<<1, 1024>>>(ln_sigma, ln_vsini, flux, n);

    int conv_blocks = (n + TILE_OUT - 1) / TILE_OUT;
    conv_kernel<<<conv_blocks, CONV_THREADS>>>(flux, n);

    int seg_threads = (n + 7) / 8;
    seg_kernel<<<(seg_threads + 255) / 256, 256>>>(ids, n);

    final_kernel<<<(out_size + 255) / 256, 256>>>((float*)d_out, out_size);
}

// round 15
// speedup vs baseline: 1.3751x; 1.1654x over previous
#include <cuda_runtime.h>
#include <math.h>

#define N_PIX_MAX 4194304
#define N_BINS    350000
#define TAPS      901
#define HALF      450
#define CHALF     900                       // composite kernel half-width
#define COMP_N    2112                      // composite kernel storage (>=1801)
#define CONV_THREADS 256
#define RPT       8                         // float2 output-pairs per thread
#define RING      8                         // u64 ring slots (elements mod 8)
#define HTILE     (CONV_THREADS * RPT)      // 2048 (per half)
#define TILE_OUT  (2 * HTILE)               // 4096 outputs per block
#define RAW2      (HTILE + 2*CHALF + 16)    // 3864 float2 window (+refill slack)
#define PAD2      (RAW2 + (RAW2 >> 3))      // bank-conflict padding (1 per 8)
#define WSH2_N    512                       // composite support slots (<=504 taps)
#define P2(i)     ((i) + ((i) >> 3))
#define JMAX      80                        // max one-sided mid-overhang (~66)
#define NC        64                        // corrected outputs per side

typedef unsigned long long u64;

// ---------------- device scratch (no allocations allowed) ----------------
__device__ float g_rot[TAPS];
__device__ float g_gauss[TAPS];
__device__ float g_comp[COMP_N];            // composite kernel K = k1 (*) k2
__device__ int   g_lo8;                     // composite support lo, 8-aligned
__device__ int   g_nblk;                    // # of 8-tap blocks
__device__ float g_corr_lo[NC];             // boundary corrections, low side
__device__ float g_corr_hi[NC];             // boundary corrections, high side
__device__ float g_sums[N_BINS];
__device__ float g_cnts[N_BINS];

// ---------------- zero the bin accumulators (graph replays!) -------------
__global__ void zero_kernel() {
    int i = blockIdx.x * blockDim.x + threadIdx.x;
    int stride = gridDim.x * blockDim.x;
    for (int j = i; j < N_BINS; j += stride) {
        g_sums[j] = 0.0f;
        g_cnts[j] = 0.0f;
    }
}

// ------- build k1, k2, composite K = k1*k2, and boundary corrections -----
__global__ void setup_kernel(const float* __restrict__ ln_sigma,
                             const float* __restrict__ ln_vsini,
                             const float* __restrict__ f, int n) {
    __shared__ float red[1024];
    __shared__ float sk1[904], sk2[904];
    __shared__ float sfl[JMAX], sfh[JMAX];      // f near low/high boundary
    __shared__ float smidl[JMAX], smidh[JMAX];  // mid[-1-t], mid[n+t]
    __shared__ int s_lo0, s_hi0, s_lo1, s_hi1;
    int tid = threadIdx.x;
    if (tid == 0) { s_lo0 = TAPS; s_hi0 = -1; s_lo1 = TAPS; s_hi1 = -1; }
    __syncthreads();

    float vsini = 0.9f + expf(ln_vsini[0]);
    float sigma = 0.01f + expf(ln_sigma[0]);

    float w  = 0.0f;   // rotational tap (pre-normalization)
    float gw = 0.0f;   // gaussian tap
    if (tid < TAPS) {
        float g = -4.5f + 0.01f * (float)tid;   // linspace(-4.5,4.5,901)
        float x  = (299792.458f * g / 10500.0f) / vsini;
        float x2 = fminf(x * x, 1.0f);
        if (x2 < 0.99999999f) {
            w = 2.0f * sqrtf(1.0f - x2);
            atomicMin(&s_lo0, tid);
            atomicMax(&s_hi0, tid);
        }
        float e = expf(-0.5f * g * g / (sigma * sigma));
        // ~4.5-sigma cutoff: truncated tail mass ~3.4e-6 relative (<< 1e-3 tol)
        if (e >= 4e-5f) {
            atomicMin(&s_lo1, tid);
            atomicMax(&s_hi1, tid);
        }
        gw = (0.01f / (sigma * sqrtf(2.0f * 3.1415926654f))) * e;
    }

    // block sum of rotational kernel for normalization
    red[tid] = w;
    __syncthreads();
    for (int s = 512; s > 0; s >>= 1) {
        if (tid < s) red[tid] += red[tid + s];
        __syncthreads();
    }
    float total = red[0];

    if (tid < TAPS) {
        float k1 = w / total;
        sk1[tid] = k1;  g_rot[tid]   = k1;
        sk2[tid] = gw;  g_gauss[tid] = gw;
    } else if (tid < 904) {
        sk1[tid] = 0.0f;
        sk2[tid] = 0.0f;
    }
    __syncthreads();

    // composite K[c] = sum_a k1[a] * k2[c-a]; support [lo0+lo1, hi0+hi1]
    int lo0 = s_lo0, hi0 = s_hi0, lo1 = s_lo1, hi1 = s_hi1;
    for (int c = tid; c < COMP_N; c += 1024) {
        float s = 0.0f;
        int a0 = max(lo0, c - hi1);
        int a1 = min(hi0, c - lo1);
        for (int a = a0; a <= a1; ++a)
            s += sk1[a] * sk2[c - a];
        g_comp[c] = s;
    }
    if (tid == 0) {
        int lo = lo0 + lo1;
        int hi = hi0 + hi1;
        int lo8 = lo & ~7;
        int nblk = ((hi - lo8 + 1) + 7) >> 3;
        if (nblk > (WSH2_N - 8) / 8) nblk = (WSH2_N - 8) / 8;  // safety clamp
        g_lo8  = lo8;
        g_nblk = nblk;
    }

    // ---- boundary corrections ----
    int JL = hi0 - HALF;  if (JL < 0) JL = 0;  if (JL > JMAX) JL = JMAX;
    int JH = HALF - lo0;  if (JH < 0) JH = 0;  if (JH > JMAX) JH = JMAX;

    for (int j = tid; j < JL; j += 1024) sfl[j] = f[j];
    for (int j = tid; j < JH; j += 1024) sfh[j] = f[n - 1 - j];  // sfh[m]=f[n-1-m]
    __syncthreads();

    // mid values outside [0,n):
    if (tid < JL) {
        int jn = tid + 1;
        float s = 0.0f;
        int mmax = hi0 - HALF - jn;
        for (int m = 0; m <= mmax; ++m)
            s += sk1[m + HALF + jn] * sfl[m];
        smidl[tid] = s;
    } else if (tid >= 128 && tid - 128 < JH) {
        int jn = tid - 127;
        float s = 0.0f;
        int mmax = HALF - jn - lo0;
        for (int m = 0; m <= mmax; ++m)
            s += sk1[HALF - jn - m] * sfh[m];
        smidh[jn - 1] = s;
    }
    __syncthreads();

    // corrections:
    if (tid >= 256 && tid < 256 + NC) {
        int i = tid - 256;
        float s = 0.0f;
        for (int jn = 1; jn <= JL; ++jn) {
            int idx = HALF - i - jn;
            if (idx >= 0) s += sk2[idx] * smidl[jn - 1];
        }
        g_corr_lo[i] = s;
    } else if (tid >= 384 && tid < 384 + NC) {
        int ii = tid - 384;                    // output i = n - NC + ii
        float s = 0.0f;
        for (int jn = 1; jn <= JH; ++jn) {
            int idx = (NC - 1 - ii) + HALF + jn;
            if (idx <= 900) s += sk2[idx] * smidh[jn - 1];
        }
        g_corr_hi[ii] = s;
    }
}

// ---- run-length accumulate 8 register values into the bin accumulators ----
__device__ __forceinline__ void seg_accum8(const int* __restrict__ ids,
                                           const float* v, int o, int n) {
    if (o >= n) return;
    if (o + RPT <= n) {
        int4 ia = *(const int4*)(ids + o);
        int4 ib = *(const int4*)(ids + o + 4);
        int id[8] = {ia.x, ia.y, ia.z, ia.w, ib.x, ib.y, ib.z, ib.w};
        int cur = id[0];
        float s = 0.0f, c = 0.0f;
#pragma unroll
        for (int r = 0; r < RPT; ++r) {
            if (id[r] != cur) {
                atomicAdd(&g_sums[cur], s);
                atomicAdd(&g_cnts[cur], c);
                cur = id[r]; s = 0.0f; c = 0.0f;
            }
            s += v[r];
            c += 1.0f;
        }
        atomicAdd(&g_sums[cur], s);
        atomicAdd(&g_cnts[cur], c);
    } else {
        for (int r = 0; r < RPT && o + r < n; ++r) {
            int id = ids[o + r];
            atomicAdd(&g_sums[id], v[r]);
            atomicAdd(&g_cnts[id], 1.0f);
        }
    }
}

// -------- fused conv + segment accumulation (no g_conv round-trip) -------
// Single pass: out[i] = sum_c K[c] * f[i+c-900], corrected at the两 edges,
// then run-length accumulated straight into the bin sums from registers.
__global__ void __launch_bounds__(CONV_THREADS, 5)
conv_kernel(const float* __restrict__ in, const int* __restrict__ ids, int n) {
    __shared__ float2 sh2[PAD2];
    __shared__ float2 wsh2[WSH2_N];

    const int lo8  = g_lo8;            // multiple of 8
    const int nblk = g_nblk;           // number of 8-tap blocks

    const int tile0 = blockIdx.x * TILE_OUT;
    const int tid   = threadIdx.x;

    for (int j = tid; j < WSH2_N; j += CONV_THREADS) {
        int c = lo8 + j;
        float wv = (c < COMP_N) ? g_comp[c] : 0.0f;
        wsh2[j] = make_float2(wv, wv);
    }
    for (int j = tid; j < RAW2; j += CONV_THREADS) {
        int g1 = tile0 - CHALF + j;
        int g2 = g1 + HTILE;
        float a = (g1 >= 0 && g1 < n) ? in[g1] : 0.0f;
        float b = (g2 >= 0 && g2 < n) ? in[g2] : 0.0f;
        sh2[P2(j)] = make_float2(a, b);
    }
    __syncthreads();

    const int base = tid * RPT;        // float2-index of first output pair
    u64 x[RING], acc[RPT];
    int roff = P2(base + lo8);         // padded index of ring start
#pragma unroll
    for (int s = 0; s < RING; ++s) {
        x[s]   = *(const u64*)&sh2[roff + s];     // P2(k0+s)=P2(k0)+s, s<8
        acc[s] = 0ull;                 // (0.0f, 0.0f)
    }
    roff += 9;                         // refill base: P2(k0+8) = P2(k0)+9

    int woff = 0;                      // weight index within wsh2
    u64 wp_cur = *(const u64*)&wsh2[0];          // prefetched packed weight
    for (int b = 0; b < nblk; ++b) {
#pragma unroll
        for (int u = 0; u < 8; ++u) {  // tap c = lo8 + 8*b + u
            u64 wp_nxt = *(const u64*)&wsh2[woff + u + 1];  // prefetch next tap
            // r=0 is the last consumer of slot u -> FMA first, then refill
            asm("fma.rn.f32x2 %0, %1, %2, %0;"
                : "+l"(acc[0]) : "l"(x[u]), "l"(wp_cur));
            u64 xfill = *(const u64*)&sh2[roff + u];        // element tap+8
#pragma unroll
            for (int r = 1; r < RPT; ++r) {
                asm("fma.rn.f32x2 %0, %1, %2, %0;"
                    : "+l"(acc[r]) : "l"(x[(u + r) & 7]), "l"(wp_cur));
            }
            x[u] = xfill;
            wp_cur = wp_nxt;
        }
        roff += 9;                     // next block's refill base
        woff += 8;
    }

    // unpack: low 32 bits = first-half output, high = second-half
    float lo_v[RPT], hi_v[RPT];
#pragma unroll
    for (int r = 0; r < RPT; ++r) {
        lo_v[r] = __int_as_float((int)(acc[r] & 0xFFFFFFFFull));
        hi_v[r] = __int_as_float((int)(acc[r] >> 32));
    }

    int o1 = tile0 + base;
    int o2 = o1 + HTILE;

    // boundary corrections (only 16 threads chip-wide take these)
    if (blockIdx.x == 0 && tid < (NC / RPT)) {
#pragma unroll
        for (int r = 0; r < RPT; ++r)
            lo_v[r] -= g_corr_lo[base + r];          // outputs 0..NC-1
    }
    if (blockIdx.x == gridDim.x - 1) {
#pragma unroll
        for (int r = 0; r < RPT; ++r) {
            int idx = o2 + r - (n - NC);
            if (idx >= 0 && idx < NC) hi_v[r] -= g_corr_hi[idx];
        }
    }

    // segment accumulation straight from registers (ids are sorted)
    seg_accum8(ids, lo_v, o1, n);
    seg_accum8(ids, hi_v, o2, n);
}

// ---------------- means, clip, drop first/last bin -----------------------
__global__ void final_kernel(float* __restrict__ out, int n_out) {
    int i = blockIdx.x * blockDim.x + threadIdx.x;
    if (i < n_out) {
        int id = i + 1;
        float c = g_cnts[id];
        float m = g_sums[id] / fmaxf(c, 1.0f);
        out[i] = fminf(fmaxf(m, 0.0f), 1.0f);
    }
}

extern "C" void kernel_launch(void* const* d_in, const int* in_sizes, int n_in,
                              void* d_out, int out_size) {
    const float* flux     = (const float*)d_in[0];
    const float* ln_sigma = (const float*)d_in[1];
    const float* ln_vsini = (const float*)d_in[2];
    const int*   ids      = (const int*)d_in[3];
    int n = in_sizes[0];

    zero_kernel<<<684, 512>>>();
    setup_kernel<<<1, 1024>>>(ln_sigma, ln_vsini, flux, n);

    int conv_blocks = (n + TILE_OUT - 1) / TILE_OUT;
    conv_kernel<<<conv_blocks, CONV_THREADS>>>(flux, ids, n);

    final_kernel<<<(out_size + 255) / 256, 256>>>((float*)d_out, out_size);
}

// round 16
// speedup vs baseline: 1.4012x; 1.0190x over previous
#include <cuda_runtime.h>
#include <math.h>

#define N_PIX_MAX 4194304
#define N_BINS    350000
#define TAPS      901
#define HALF      450
#define CHALF     900                       // composite kernel half-width
#define COMP_N    2112                      // composite kernel storage (>=1801)
#define CONV_THREADS 128
#define RPT       8                         // float2 output-pairs per thread
#define RING      8                         // u64 ring slots (elements mod 8)
#define HTILE     (CONV_THREADS * RPT)      // 1024 (per half)
#define TILE_OUT  (2 * HTILE)               // 2048 outputs per block
#define RAW2      (HTILE + 2*CHALF + 16)    // 2840 float2 window (+refill slack)
#define PAD2      (RAW2 + (RAW2 >> 3))      // bank-conflict padding (1 per 8)
#define WSH2_N    512                       // composite support slots (<=504 taps)
#define P2(i)     ((i) + ((i) >> 3))
#define JMAX      80                        // max one-sided mid-overhang (~66)
#define NC        64                        // corrected outputs per side

typedef unsigned long long u64;

// ---------------- device scratch (no allocations allowed) ----------------
__device__ float g_rot[TAPS];
__device__ float g_gauss[TAPS];
__device__ float g_comp[COMP_N];            // composite kernel K = k1 (*) k2
__device__ int   g_lo8;                     // composite support lo, 8-aligned
__device__ int   g_nblk;                    // # of 8-tap blocks
__device__ float g_corr_lo[NC];             // boundary corrections, low side
__device__ float g_corr_hi[NC];             // boundary corrections, high side
__device__ __align__(16) float g_sums[N_BINS];
__device__ __align__(16) float g_cnts[N_BINS];

// ---------------- zero the bin accumulators (graph replays!) -------------
__global__ void zero_kernel() {
    int i = blockIdx.x * blockDim.x + threadIdx.x;
    int stride = gridDim.x * blockDim.x;
    float4 z = make_float4(0.f, 0.f, 0.f, 0.f);
    for (int j = i; j < N_BINS / 4; j += stride) {
        ((float4*)g_sums)[j] = z;
        ((float4*)g_cnts)[j] = z;
    }
}

// ------- build k1, k2, composite K = k1*k2, and boundary corrections -----
__global__ void setup_kernel(const float* __restrict__ ln_sigma,
                             const float* __restrict__ ln_vsini,
                             const float* __restrict__ f, int n) {
    __shared__ float red[1024];
    __shared__ float sk1[904], sk2[904];
    __shared__ float sfl[JMAX], sfh[JMAX];      // f near low/high boundary
    __shared__ float smidl[JMAX], smidh[JMAX];  // mid[-1-t], mid[n+t]
    __shared__ int s_lo0, s_hi0, s_lo1, s_hi1;
    int tid = threadIdx.x;
    if (tid == 0) { s_lo0 = TAPS; s_hi0 = -1; s_lo1 = TAPS; s_hi1 = -1; }
    __syncthreads();

    float vsini = 0.9f + expf(ln_vsini[0]);
    float sigma = 0.01f + expf(ln_sigma[0]);

    float w  = 0.0f;   // rotational tap (pre-normalization)
    float gw = 0.0f;   // gaussian tap
    if (tid < TAPS) {
        float g = -4.5f + 0.01f * (float)tid;   // linspace(-4.5,4.5,901)
        float x  = (299792.458f * g / 10500.0f) / vsini;
        float x2 = fminf(x * x, 1.0f);
        if (x2 < 0.99999999f) {
            w = 2.0f * sqrtf(1.0f - x2);
            atomicMin(&s_lo0, tid);
            atomicMax(&s_hi0, tid);
        }
        float e = expf(-0.5f * g * g / (sigma * sigma));
        // ~4.5-sigma cutoff: truncated tail mass ~3.4e-6 relative (<< 1e-3 tol)
        if (e >= 4e-5f) {
            atomicMin(&s_lo1, tid);
            atomicMax(&s_hi1, tid);
        }
        gw = (0.01f / (sigma * sqrtf(2.0f * 3.1415926654f))) * e;
    }

    // block sum of rotational kernel for normalization
    red[tid] = w;
    __syncthreads();
    for (int s = 512; s > 0; s >>= 1) {
        if (tid < s) red[tid] += red[tid + s];
        __syncthreads();
    }
    float total = red[0];

    if (tid < TAPS) {
        float k1 = w / total;
        sk1[tid] = k1;  g_rot[tid]   = k1;
        sk2[tid] = gw;  g_gauss[tid] = gw;
    } else if (tid < 904) {
        sk1[tid] = 0.0f;
        sk2[tid] = 0.0f;
    }
    __syncthreads();

    // composite K[c] = sum_a k1[a] * k2[c-a]; support [lo0+lo1, hi0+hi1]
    int lo0 = s_lo0, hi0 = s_hi0, lo1 = s_lo1, hi1 = s_hi1;
    for (int c = tid; c < COMP_N; c += 1024) {
        float s = 0.0f;
        int a0 = max(lo0, c - hi1);
        int a1 = min(hi0, c - lo1);
        for (int a = a0; a <= a1; ++a)
            s += sk1[a] * sk2[c - a];
        g_comp[c] = s;
    }
    if (tid == 0) {
        int lo = lo0 + lo1;
        int hi = hi0 + hi1;
        int lo8 = lo & ~7;
        int nblk = ((hi - lo8 + 1) + 7) >> 3;
        if (nblk > (WSH2_N - 8) / 8) nblk = (WSH2_N - 8) / 8;  // safety clamp
        g_lo8  = lo8;
        g_nblk = nblk;
    }

    // ---- boundary corrections ----
    int JL = hi0 - HALF;  if (JL < 0) JL = 0;  if (JL > JMAX) JL = JMAX;
    int JH = HALF - lo0;  if (JH < 0) JH = 0;  if (JH > JMAX) JH = JMAX;

    for (int j = tid; j < JL; j += 1024) sfl[j] = f[j];
    for (int j = tid; j < JH; j += 1024) sfh[j] = f[n - 1 - j];  // sfh[m]=f[n-1-m]
    __syncthreads();

    // mid values outside [0,n):
    if (tid < JL) {
        int jn = tid + 1;
        float s = 0.0f;
        int mmax = hi0 - HALF - jn;
        for (int m = 0; m <= mmax; ++m)
            s += sk1[m + HALF + jn] * sfl[m];
        smidl[tid] = s;
    } else if (tid >= 128 && tid - 128 < JH) {
        int jn = tid - 127;
        float s = 0.0f;
        int mmax = HALF - jn - lo0;
        for (int m = 0; m <= mmax; ++m)
            s += sk1[HALF - jn - m] * sfh[m];
        smidh[jn - 1] = s;
    }
    __syncthreads();

    // corrections:
    if (tid >= 256 && tid < 256 + NC) {
        int i = tid - 256;
        float s = 0.0f;
        for (int jn = 1; jn <= JL; ++jn) {
            int idx = HALF - i - jn;
            if (idx >= 0) s += sk2[idx] * smidl[jn - 1];
        }
        g_corr_lo[i] = s;
    } else if (tid >= 384 && tid < 384 + NC) {
        int ii = tid - 384;                    // output i = n - NC + ii
        float s = 0.0f;
        for (int jn = 1; jn <= JH; ++jn) {
            int idx = (NC - 1 - ii) + HALF + jn;
            if (idx <= 900) s += sk2[idx] * smidh[jn - 1];
        }
        g_corr_hi[ii] = s;
    }
}

// ---- run-length accumulate 8 register values into the bin accumulators ----
__device__ __forceinline__ void seg_accum8(const int* __restrict__ ids,
                                           const float* v, int o, int n) {
    if (o >= n) return;
    if (o + RPT <= n) {
        int4 ia = *(const int4*)(ids + o);
        int4 ib = *(const int4*)(ids + o + 4);
        int id[8] = {ia.x, ia.y, ia.z, ia.w, ib.x, ib.y, ib.z, ib.w};
        int cur = id[0];
        float s = 0.0f, c = 0.0f;
#pragma unroll
        for (int r = 0; r < RPT; ++r) {
            if (id[r] != cur) {
                atomicAdd(&g_sums[cur], s);
                atomicAdd(&g_cnts[cur], c);
                cur = id[r]; s = 0.0f; c = 0.0f;
            }
            s += v[r];
            c += 1.0f;
        }
        atomicAdd(&g_sums[cur], s);
        atomicAdd(&g_cnts[cur], c);
    } else {
        for (int r = 0; r < RPT && o + r < n; ++r) {
            int id = ids[o + r];
            atomicAdd(&g_sums[id], v[r]);
            atomicAdd(&g_cnts[id], 1.0f);
        }
    }
}

// -------- fused conv + segment accumulation (no g_conv round-trip) -------
// 128 threads/block, TILE_OUT=2048 -> grid=2048 over 7 CTAs/SM * 148 SMs
// = 1036 slots/wave -> 1.98 waves (tail efficiency ~0.99 vs 0.69 before).
__global__ void __launch_bounds__(CONV_THREADS, 7)
conv_kernel(const float* __restrict__ in, const int* __restrict__ ids, int n) {
    __shared__ float2 sh2[PAD2];
    __shared__ float2 wsh2[WSH2_N];

    const int lo8  = g_lo8;            // multiple of 8
    const int nblk = g_nblk;           // number of 8-tap blocks

    const int tile0 = blockIdx.x * TILE_OUT;
    const int tid   = threadIdx.x;

    for (int j = tid; j < WSH2_N; j += CONV_THREADS) {
        int c = lo8 + j;
        float wv = (c < COMP_N) ? g_comp[c] : 0.0f;
        wsh2[j] = make_float2(wv, wv);
    }
    for (int j = tid; j < RAW2; j += CONV_THREADS) {
        int g1 = tile0 - CHALF + j;
        int g2 = g1 + HTILE;
        float a = (g1 >= 0 && g1 < n) ? in[g1] : 0.0f;
        float b = (g2 >= 0 && g2 < n) ? in[g2] : 0.0f;
        sh2[P2(j)] = make_float2(a, b);
    }
    __syncthreads();

    const int base = tid * RPT;        // float2-index of first output pair
    u64 x[RING], acc[RPT];
    int roff = P2(base + lo8);         // padded index of ring start
#pragma unroll
    for (int s = 0; s < RING; ++s) {
        x[s]   = *(const u64*)&sh2[roff + s];     // P2(k0+s)=P2(k0)+s, s<8
        acc[s] = 0ull;                 // (0.0f, 0.0f)
    }
    roff += 9;                         // refill base: P2(k0+8) = P2(k0)+9

    int woff = 0;                      // weight index within wsh2
    u64 wp_cur = *(const u64*)&wsh2[0];          // prefetched packed weight
    for (int b = 0; b < nblk; ++b) {
#pragma unroll
        for (int u = 0; u < 8; ++u) {  // tap c = lo8 + 8*b + u
            u64 wp_nxt = *(const u64*)&wsh2[woff + u + 1];  // prefetch next tap
            // r=0 is the last consumer of slot u -> FMA first, then refill
            asm("fma.rn.f32x2 %0, %1, %2, %0;"
                : "+l"(acc[0]) : "l"(x[u]), "l"(wp_cur));
            u64 xfill = *(const u64*)&sh2[roff + u];        // element tap+8
#pragma unroll
            for (int r = 1; r < RPT; ++r) {
                asm("fma.rn.f32x2 %0, %1, %2, %0;"
                    : "+l"(acc[r]) : "l"(x[(u + r) & 7]), "l"(wp_cur));
            }
            x[u] = xfill;
            wp_cur = wp_nxt;
        }
        roff += 9;                     // next block's refill base
        woff += 8;
    }

    // unpack: low 32 bits = first-half output, high = second-half
    float lo_v[RPT], hi_v[RPT];
#pragma unroll
    for (int r = 0; r < RPT; ++r) {
        lo_v[r] = __int_as_float((int)(acc[r] & 0xFFFFFFFFull));
        hi_v[r] = __int_as_float((int)(acc[r] >> 32));
    }

    int o1 = tile0 + base;
    int o2 = o1 + HTILE;

    // boundary corrections (only 16 threads chip-wide take these)
    if (blockIdx.x == 0 && tid < (NC / RPT)) {
#pragma unroll
        for (int r = 0; r < RPT; ++r)
            lo_v[r] -= g_corr_lo[base + r];          // outputs 0..NC-1
    }
    if (blockIdx.x == gridDim.x - 1) {
#pragma unroll
        for (int r = 0; r < RPT; ++r) {
            int idx = o2 + r - (n - NC);
            if (idx >= 0 && idx < NC) hi_v[r] -= g_corr_hi[idx];
        }
    }

    // segment accumulation straight from registers (ids are sorted)
    seg_accum8(ids, lo_v, o1, n);
    seg_accum8(ids, hi_v, o2, n);
}

// ---------------- means, clip, drop first/last bin -----------------------
// Vectorized: thread t handles bins 4t..4t+3 (aligned float4 loads),
// writes out[b-1] for b in [1, n_out] (scalar stores absorb the shift).
__global__ void final_kernel(float* __restrict__ out, int n_out) {
    int t = blockIdx.x * blockDim.x + threadIdx.x;
    int b0 = t * 4;
    if (b0 >= N_BINS) return;
    float4 s4 = ((const float4*)g_sums)[t];
    float4 c4 = ((const float4*)g_cnts)[t];
    float sv[4] = {s4.x, s4.y, s4.z, s4.w};
    float cv[4] = {c4.x, c4.y, c4.z, c4.w};
#pragma unroll
    for (int r = 0; r < 4; ++r) {
        int b = b0 + r;                // bin id
        if (b >= 1 && b <= n_out) {
            float m = sv[r] / fmaxf(cv[r], 1.0f);
            out[b - 1] = fminf(fmaxf(m, 0.0f), 1.0f);
        }
    }
}

extern "C" void kernel_launch(void* const* d_in, const int* in_sizes, int n_in,
                              void* d_out, int out_size) {
    const float* flux     = (const float*)d_in[0];
    const float* ln_sigma = (const float*)d_in[1];
    const float* ln_vsini = (const float*)d_in[2];
    const int*   ids      = (const int*)d_in[3];
    int n = in_sizes[0];

    zero_kernel<<<342, 256>>>();
    setup_kernel<<<1, 1024>>>(ln_sigma, ln_vsini, flux, n);

    int conv_blocks = (n + TILE_OUT - 1) / TILE_OUT;
    conv_kernel<<<conv_blocks, CONV_THREADS>>>(flux, ids, n);

    final_kernel<<<(N_BINS / 4 + 255) / 256, 256>>>((float*)d_out, out_size);
}